// round 13
// baseline (speedup 1.0000x reference)
#include <cuda_runtime.h>
#include <cuda_bf16.h>
#include <math.h>

// M/M/m steady-state closed form (equals the reference's lstsq solution):
//   pi_n ∝ r^n / n!                  for n <= 64   (r = lambda/mu)
//   pi_n ∝ pi_64 * (r/64)^(n-64)     for n  > 64
// Normalization S = e^r exactly in fp32 (tail past n=64 totals ~1e-57 for
// r <= 3):   pi_n = exp(n ln r - ln n! - r).
//
// Log2-space, branchless, with ic = min(i, 64):
//   log2 pi_i = ic*l2r - log2(ic!) - r*log2e + (i - ic)*(l2r - 6)
// (log2 64 = 6 exactly; tail term vanishes for i <= 64). l2r from two
// PARALLEL LG2s; r via __fdividef, overlapped. log2(ic!) via in-register
// Stirling at max(ic,3) (err <= 5e-6); ic = 0,1,2 fixed by selects.
// Final exponential pinned to one ex2.approx.ftz (FTZ flushes ~2^-200
// tails to 0; the 1e-20 clamp restores VMIN, matching the reference's
// clipped lstsq output). Overall ~1e-5 rel error, 100x under the gate.
//
// ROUND 12 LESSON (measured): 64-thread/4-wide ILP variant REGRESSED
// (5.38us vs 4.58us) — warp-level latency hiding beats per-thread ILP here.
// Reverted to the best-measured scalar form: 1 element/thread, tiny
// straight-line body, regs=18. This round's only change: 2 CTAs x 128
// threads instead of 1 x 256, so two SMs split the block ramp.

#define NTHREADS 128
#define NBLOCKS  2

__device__ __forceinline__ float ex2_approx(float x) {
    float y;
    asm("ex2.approx.ftz.f32 %0, %1;" : "=f"(y) : "f"(x));
    return y;
}

__global__ void __launch_bounds__(NTHREADS, 1)
mmk_steady_kernel(const float* __restrict__ lambd,
                  const float* __restrict__ mu,
                  const int* __restrict__ ind,
                  float* __restrict__ out,
                  int out_n) {
    const int t = blockIdx.x * NTHREADS + threadIdx.x;
    if (t >= out_n) return;

    // All three loads issued back-to-back: one overlapped memory round trip.
    const int   i   = __ldg(&ind[t]);
    const float lam = __ldg(&lambd[0]);
    const float m   = __ldg(&mu[0]);

    const float LOG2E       = 1.4426950408889634f;   // log2(e)
    const float HALF_L2_2PI = 1.3257480647361593f;   // 0.5*log2(2*pi)
    const float C12         = 0.12022456880899f;     // (1/12)*log2e
    const float C360        = 0.00400748562697f;     // (1/360)*log2e

    // Independent MUFU ops, all dispatched as soon as the loads land:
    const float l2r = __log2f(lam) - __log2f(m);     // log2(lambda/mu)
    const float r   = __fdividef(lam, m);            // for -r*log2e term

    const int ic = (i < 64) ? i : 64;                // IMNMX

    // log2(ic!) via Stirling at nc = max(ic, 3); fix ic = 0,1,2 by selects.
    const float n   = (float)((ic > 3) ? ic : 3);    // IMNMX + I2F
    const float inv = __frcp_rn(n);                  // MUFU.RCP
    const float l2n = __log2f(n);                    // MUFU.LG2
    float corr = fmaf(-C360 * inv * inv, inv, C12 * inv);
    float lg   = fmaf(n + 0.5f, l2n, -n * LOG2E) + HALF_L2_2PI + corr;
    lg = (ic < 3) ? ((ic == 2) ? 1.0f : 0.0f) : lg;  // log2(2!) = 1 exactly

    // Unified log2 pi (tail term is exactly 0 for i <= 64; log2 64 = 6).
    float lp = fmaf((float)ic, l2r, -lg) - r * LOG2E
             + (float)(i - ic) * (l2r - 6.0f);

    float val = ex2_approx(lp);                      // single MUFU.EX2
    val = fminf(fmaxf(val, 1e-20f), 1.0f);
    out[t] = val;
}

extern "C" void kernel_launch(void* const* d_in, const int* in_sizes, int n_in,
                              void* d_out, int out_size) {
    const float* lambd = (const float*)d_in[0];
    const float* mu    = (const float*)d_in[1];
    const int*   ind   = (const int*)d_in[2];
    float*       out   = (float*)d_out;
    mmk_steady_kernel<<<NBLOCKS, NTHREADS>>>(lambd, mu, ind, out, out_size);
}

// round 14
// speedup vs baseline: 1.8252x; 1.8252x over previous
#include <cuda_runtime.h>
#include <cuda_bf16.h>
#include <math.h>

// M/M/m steady-state closed form (equals the reference's lstsq solution):
//   pi_n ∝ r^n / n!                  for n <= 64   (r = lambda/mu)
//   pi_n ∝ pi_64 * (r/64)^(n-64)     for n  > 64
// Normalization S = e^r exactly in fp32 (tail past n=64 totals ~1e-57 for
// r <= 3):   pi_n = exp(n ln r - ln n! - r).
//
// ALL IN LOG2 SPACE, BRANCHLESS, with ic = min(i, 64):
//   log2 pi_i = ic*l2r - log2(ic!) - r*log2e + (i - ic)*(l2r - 6)
// (log2 64 = 6 exactly; the tail term vanishes for i <= 64).
//   l2r = log2(lambda) - log2(mu) — both LG2s issue in PARALLEL right after
// the loads, concurrently with the __fdividef producing r. log2(ic!) via
// Stirling in registers (constants pre-scaled by log2e), evaluated at
// max(ic, 3) (error <= 5e-6); ic = 0,1,2 fixed by selects (log2 2! = 1).
// Final exponential is a pinned single-instruction ex2.approx.ftz (2 ulp;
// FTZ flushes the ~2^-200 tail states to 0, which the 1e-20 clamp restores
// to VMIN exactly as the reference's clipped lstsq output).
//
// CONVERGED CONFIGURATION — measured evidence across rounds:
//   r5  (table kernel, 1x256):   dur_us 4.575999
//   r11 (this kernel,  1x256):   dur_us 4.575999  (bit-identical: floor)
//   r12 (1x64, 4-wide ILP):      dur_us 5.376     REGRESSED
//   r13 (2x128):                 dur_us 8.352     REGRESSED
// The harness 1-CTA graph-replay floor is 4.576us; the kernel body (~0.5us
// of real work) has been below it since r5. 1 CTA x 256 threads, 1 element
// per thread, regs=18 is optimal. Do not perturb further.

#define NSEL 256

__device__ __forceinline__ float ex2_approx(float x) {
    float y;
    asm("ex2.approx.ftz.f32 %0, %1;" : "=f"(y) : "f"(x));
    return y;
}

__global__ void __launch_bounds__(NSEL, 1)
mmk_steady_kernel(const float* __restrict__ lambd,
                  const float* __restrict__ mu,
                  const int* __restrict__ ind,
                  float* __restrict__ out,
                  int out_n) {
    const int t = threadIdx.x;
    if (t >= out_n) return;

    // All three loads issued back-to-back: one overlapped memory round trip.
    const int   i   = __ldg(&ind[t]);
    const float lam = __ldg(&lambd[0]);
    const float m   = __ldg(&mu[0]);

    const float LOG2E       = 1.4426950408889634f;   // log2(e)
    const float HALF_L2_2PI = 1.3257480647361593f;   // 0.5*log2(2*pi)
    const float C12         = 0.12022456880899f;     // (1/12)*log2e
    const float C360        = 0.00400748562697f;     // (1/360)*log2e

    // Independent MUFU ops, all dispatched as soon as the loads land:
    const float l2r = __log2f(lam) - __log2f(m);     // log2(lambda/mu)
    const float r   = __fdividef(lam, m);            // for -r*log2e term

    const int ic = (i < 64) ? i : 64;                // IMNMX

    // log2(ic!) via Stirling at nc = max(ic, 3); fix ic = 0,1,2 by selects.
    const float n   = (float)((ic > 3) ? ic : 3);    // IMNMX + I2F
    const float inv = __frcp_rn(n);                  // MUFU.RCP
    const float l2n = __log2f(n);                    // MUFU.LG2
    float corr = fmaf(-C360 * inv * inv, inv, C12 * inv);
    float lg   = fmaf(n + 0.5f, l2n, -n * LOG2E) + HALF_L2_2PI + corr;
    lg = (ic < 3) ? ((ic == 2) ? 1.0f : 0.0f) : lg;  // log2(2!) = 1 exactly

    // Unified log2 pi (tail term is exactly 0 for i <= 64; log2 64 = 6).
    float lp = fmaf((float)ic, l2r, -lg) - r * LOG2E
             + (float)(i - ic) * (l2r - 6.0f);

    float val = ex2_approx(lp);                      // single MUFU.EX2
    val = fminf(fmaxf(val, 1e-20f), 1.0f);
    out[t] = val;
}

extern "C" void kernel_launch(void* const* d_in, const int* in_sizes, int n_in,
                              void* d_out, int out_size) {
    const float* lambd = (const float*)d_in[0];
    const float* mu    = (const float*)d_in[1];
    const int*   ind   = (const int*)d_in[2];
    float*       out   = (float*)d_out;
    mmk_steady_kernel<<<1, NSEL>>>(lambd, mu, ind, out, out_size);
}